// round 1
// baseline (speedup 1.0000x reference)
#include <cuda_runtime.h>
#include <math.h>
#include <stdio.h>

#define N_NODES 20000
#define N_EDGES 400000
#define DIM 128
#define NB 16
#define ZD 16
#define UW (NB*DIM)   // 2048

// ---------------- device scratch (static, no allocations) ----------------
__device__ float g_zi16[N_NODES*ZD];        // layer-0 input features (Z[species])
__device__ float g_zi[N_NODES*DIM];         // current activation
__device__ float g_zself[N_NODES*DIM];      // pre-activation accumulator
__device__ float g_h[N_NODES*DIM];          // onsite hidden
__device__ float g_U[(size_t)N_NODES*UW];   // per-node message basis: U[n][b][d] = z[n] @ V[b]
__device__ float g_Vt[DIM*UW];              // transposed V (K x NB*DIM), reused across layers

__device__ __forceinline__ float silu_f(float x) {
    return x / (1.0f + __expf(-x));
}

// ---------------- small kernels ----------------
__global__ void k_embed(const int* __restrict__ species, const float* __restrict__ Z) {
    int t = blockIdx.x * blockDim.x + threadIdx.x;
    if (t < N_NODES * ZD) {
        int n = t >> 4, k = t & 15;
        g_zi16[t] = Z[species[n] * ZD + k];
    }
}

// V: (NB, K, DIM) row-major  ->  g_Vt: (K, NB*DIM) so U = A[ M x K ] @ Vt
__global__ void k_transpose(const float* __restrict__ V, int K) {
    int t = blockIdx.x * blockDim.x + threadIdx.x;
    if (t < K * UW) {
        int j = t % UW;       // b*128 + d
        int k = t / UW;
        int b = j >> 7, d = j & 127;
        g_Vt[t] = V[((size_t)b * K + k) * DIM + d];
    }
}

__global__ void k_silu_zself() {
    int t = blockIdx.x * blockDim.x + threadIdx.x;
    if (t < N_NODES * DIM) g_zi[t] = silu_f(g_zself[t]);
}

// write zis layer-0 slot: out[N*DIM + n*256 + d]
__global__ void k_copy0(float* __restrict__ out) {
    int t = blockIdx.x * blockDim.x + threadIdx.x;
    if (t < N_NODES * DIM) {
        int n = t >> 7, d = t & 127;
        out[N_NODES * DIM + n * 2 * DIM + d] = g_zi[t];
    }
}

// write final zi and zis layer-1 slot
__global__ void k_copy1(float* __restrict__ out) {
    int t = blockIdx.x * blockDim.x + threadIdx.x;
    if (t < N_NODES * DIM) {
        int n = t >> 7, d = t & 127;
        float v = g_zi[t];
        out[t] = v;
        out[N_NODES * DIM + n * 2 * DIM + DIM + d] = v;
    }
}

// ---------------- generic fused SGEMM ----------------
// C[M x N] = epilogue(A[M x K] @ B[K x N]); N, K multiples of 16/64 as used.
// BM=BN=64, BK=16, 256 threads, 4x4 register tile.
// bias: optional (+bias[n]); act: silu; Cadd: optional residual (+Cadd[m*ldc+n]).
__global__ __launch_bounds__(256, 2) void k_gemm(
    const float* __restrict__ A, const float* __restrict__ B,
    const float* __restrict__ bias, const float* __restrict__ Cadd,
    float* __restrict__ C,
    int M, int K, int lda, int ldb, int ldc, int act)
{
    __shared__ float As[16][64];
    __shared__ float Bs[16][64];

    const int t  = threadIdx.x;
    const int tx = t & 15, ty = t >> 4;
    const int m0 = blockIdx.y * 64, n0 = blockIdx.x * 64;

    const int mload = t >> 2, kq = t & 3;     // A loader: row m0+mload, 4 k's
    const int kload = t >> 4;                 // B loader: row k0+kload
    const int nq    = (t & 15) * 4;           // B loader: 4 n's

    float acc[4][4];
    #pragma unroll
    for (int i = 0; i < 4; i++)
        #pragma unroll
        for (int j = 0; j < 4; j++) acc[i][j] = 0.0f;

    for (int k0 = 0; k0 < K; k0 += 16) {
        float4 av = make_float4(0.f, 0.f, 0.f, 0.f);
        int gm = m0 + mload;
        if (gm < M)
            av = *(const float4*)&A[(size_t)gm * lda + k0 + kq * 4];
        As[kq * 4 + 0][mload] = av.x;
        As[kq * 4 + 1][mload] = av.y;
        As[kq * 4 + 2][mload] = av.z;
        As[kq * 4 + 3][mload] = av.w;

        float4 bv = *(const float4*)&B[(size_t)(k0 + kload) * ldb + n0 + nq];
        *(float4*)&Bs[kload][nq] = bv;

        __syncthreads();

        #pragma unroll
        for (int kk = 0; kk < 16; kk++) {
            float4 a = *(float4*)&As[kk][ty * 4];
            float4 b = *(float4*)&Bs[kk][tx * 4];
            float ar[4] = {a.x, a.y, a.z, a.w};
            float br[4] = {b.x, b.y, b.z, b.w};
            #pragma unroll
            for (int i = 0; i < 4; i++)
                #pragma unroll
                for (int j = 0; j < 4; j++)
                    acc[i][j] += ar[i] * br[j];
        }
        __syncthreads();
    }

    #pragma unroll
    for (int i = 0; i < 4; i++) {
        int m = m0 + ty * 4 + i;
        if (m >= M) continue;
        #pragma unroll
        for (int j = 0; j < 4; j++) {
            int n = n0 + tx * 4 + j;
            float v = acc[i][j];
            if (bias) v += bias[n];
            if (act)  v = silu_f(v);
            if (Cadd) v += Cadd[(size_t)m * ldc + n];
            C[(size_t)m * ldc + n] = v;
        }
    }
}

// ---------------- edge kernel ----------------
// One warp per edge. mij[d] = sum_b s[b]*sw * U[dst][b][d]; atomic add into zself[src].
__global__ __launch_bounds__(256) void k_edge(
    const int* __restrict__ esrc, const int* __restrict__ edst,
    const float* __restrict__ dist, const float* __restrict__ sw)
{
    const int wid  = threadIdx.x >> 5;
    const int lane = threadIdx.x & 31;
    const int e = blockIdx.x * 8 + wid;
    if (e >= N_EDGES) return;

    const int src = esrc[e];
    const int dst = edst[e];

    // radial basis * switch, lanes 0..15 hold b=0..15 (lanes 16..31 duplicate)
    float sval;
    {
        const float sigma  = 0.8f / 15.0f;
        const float rsigma = 15.0f / 0.8f;
        float rinv = 1.0f / dist[e];
        int b = lane & 15;
        float mu = 0.2f + (float)b * sigma;
        float x = (rinv - mu) * rsigma;
        sval = __expf(-0.5f * x * x) * sw[e];
    }

    const float4* Up = (const float4*)&g_U[(size_t)dst * UW];
    float4 acc = make_float4(0.f, 0.f, 0.f, 0.f);
    #pragma unroll
    for (int b = 0; b < 16; b++) {
        float sb = __shfl_sync(0xffffffffu, sval, b);
        float4 u = Up[b * 32 + lane];
        acc.x += sb * u.x;
        acc.y += sb * u.y;
        acc.z += sb * u.z;
        acc.w += sb * u.w;
    }

    float* zp = &g_zself[(size_t)src * DIM + lane * 4];
    atomicAdd(zp + 0, acc.x);
    atomicAdd(zp + 1, acc.y);
    atomicAdd(zp + 2, acc.z);
    atomicAdd(zp + 3, acc.w);
}

// ---------------- host driver ----------------
extern "C" void kernel_launch(void* const* d_in, const int* in_sizes, int n_in,
                              void* d_out, int out_size)
{
    const int*   species = (const int*)  d_in[0];
    const int*   esrc    = (const int*)  d_in[1];
    const int*   edst    = (const int*)  d_in[2];
    const float* dist    = (const float*)d_in[3];
    const float* swp     = (const float*)d_in[4];
    const float* Z       = (const float*)d_in[5];
    const float* Ws0     = (const float*)d_in[6];
    const float* bs0     = (const float*)d_in[7];
    const float* V0      = (const float*)d_in[8];
    const float* Ws1     = (const float*)d_in[9];
    const float* bs1     = (const float*)d_in[10];
    const float* V1      = (const float*)d_in[11];
    const float* Won_a   = (const float*)d_in[12];
    const float* bon_a   = (const float*)d_in[13];
    const float* Won_b   = (const float*)d_in[14];
    const float* bon_b   = (const float*)d_in[15];
    float* out = (float*)d_out;

    // resolve device scratch addresses (no allocation; these are module globals)
    float *zi16, *zi, *zself, *h, *U, *Vt;
    cudaGetSymbolAddress((void**)&zi16,  g_zi16);
    cudaGetSymbolAddress((void**)&zi,    g_zi);
    cudaGetSymbolAddress((void**)&zself, g_zself);
    cudaGetSymbolAddress((void**)&h,     g_h);
    cudaGetSymbolAddress((void**)&U,     g_U);
    cudaGetSymbolAddress((void**)&Vt,    g_Vt);

    const int ND = N_NODES * DIM;            // 2,560,000
    dim3 gemm128(DIM / 64, (N_NODES + 63) / 64);   // N=128
    dim3 gemmU  (UW  / 64, (N_NODES + 63) / 64);   // N=2048

    // ---- layer 0 ----
    k_embed<<<(N_NODES * ZD + 255) / 256, 256>>>(species, Z);
    k_transpose<<<(ZD * UW + 255) / 256, 256>>>(V0, ZD);

    // zself = zi16 @ Ws0 + bs0
    k_gemm<<<gemm128, 256>>>(zi16, Ws0, bs0, nullptr, zself,
                             N_NODES, ZD, ZD, DIM, DIM, 0);
    // U = zi16 @ V0t
    k_gemm<<<gemmU, 256>>>(zi16, Vt, nullptr, nullptr, U,
                           N_NODES, ZD, ZD, UW, UW, 0);

    k_edge<<<N_EDGES / 8, 256>>>(esrc, edst, dist, swp);
    k_silu_zself<<<(ND + 255) / 256, 256>>>();

    for (int j = 0; j < 3; j++) {
        const float* Wa = Won_a + (size_t)(0 * 3 + j) * DIM * DIM;
        const float* ba = bon_a + (size_t)(0 * 3 + j) * DIM;
        const float* Wb = Won_b + (size_t)(0 * 3 + j) * DIM * DIM;
        const float* bb = bon_b + (size_t)(0 * 3 + j) * DIM;
        k_gemm<<<gemm128, 256>>>(zi, Wa, ba, nullptr, h,
                                 N_NODES, DIM, DIM, DIM, DIM, 1);   // h = silu(zi@Wa+ba)
        k_gemm<<<gemm128, 256>>>(h, Wb, bb, zi, zi,
                                 N_NODES, DIM, DIM, DIM, DIM, 0);   // zi = zi + h@Wb+bb
    }
    k_copy0<<<(ND + 255) / 256, 256>>>(out);

    // ---- layer 1 ----
    k_transpose<<<(DIM * UW + 255) / 256, 256>>>(V1, DIM);

    k_gemm<<<gemm128, 256>>>(zi, Ws1, bs1, nullptr, zself,
                             N_NODES, DIM, DIM, DIM, DIM, 0);
    k_gemm<<<gemmU, 256>>>(zi, Vt, nullptr, nullptr, U,
                           N_NODES, DIM, DIM, UW, UW, 0);

    k_edge<<<N_EDGES / 8, 256>>>(esrc, edst, dist, swp);
    k_silu_zself<<<(ND + 255) / 256, 256>>>();

    for (int j = 0; j < 3; j++) {
        const float* Wa = Won_a + (size_t)(1 * 3 + j) * DIM * DIM;
        const float* ba = bon_a + (size_t)(1 * 3 + j) * DIM;
        const float* Wb = Won_b + (size_t)(1 * 3 + j) * DIM * DIM;
        const float* bb = bon_b + (size_t)(1 * 3 + j) * DIM;
        k_gemm<<<gemm128, 256>>>(zi, Wa, ba, nullptr, h,
                                 N_NODES, DIM, DIM, DIM, DIM, 1);
        k_gemm<<<gemm128, 256>>>(h, Wb, bb, zi, zi,
                                 N_NODES, DIM, DIM, DIM, DIM, 0);
    }
    k_copy1<<<(ND + 255) / 256, 256>>>(out);
}

// round 2
// speedup vs baseline: 1.4499x; 1.4499x over previous
#include <cuda_runtime.h>
#include <cuda_fp16.h>
#include <math.h>

#define N_NODES 20000
#define N_EDGES 400000
#define DIM 128
#define NB 16
#define ZD 16
#define UW (NB*DIM)   // 2048

// ---------------- device scratch (static, no allocations) ----------------
__device__ float  g_zi16[N_NODES*ZD];        // layer-0 input features (Z[species])
__device__ float  g_zi[N_NODES*DIM];         // current activation
__device__ float  g_zself[N_NODES*DIM];      // pre-activation accumulator
__device__ float  g_h[N_NODES*DIM];          // onsite hidden
__device__ __half g_Uh[(size_t)N_NODES*UW];  // per-node message basis (fp16): U[n][b][d]
__device__ float  g_Vt[DIM*UW];              // transposed V (K x NB*DIM)

__device__ __forceinline__ float silu_f(float x) {
    return x / (1.0f + __expf(-x));
}

// ---------------- small kernels ----------------
__global__ void k_embed(const int* __restrict__ species, const float* __restrict__ Z) {
    int t = blockIdx.x * blockDim.x + threadIdx.x;
    if (t < N_NODES * ZD) {
        int n = t >> 4, k = t & 15;
        g_zi16[t] = Z[species[n] * ZD + k];
    }
}

// V: (NB, K, DIM) row-major  ->  g_Vt: (K, NB*DIM)
__global__ void k_transpose(const float* __restrict__ V, int K) {
    int t = blockIdx.x * blockDim.x + threadIdx.x;
    if (t < K * UW) {
        int j = t % UW;       // b*128 + d
        int k = t / UW;
        int b = j >> 7, d = j & 127;
        g_Vt[t] = V[((size_t)b * K + k) * DIM + d];
    }
}

__global__ void k_silu_zself() {
    int t = blockIdx.x * blockDim.x + threadIdx.x;
    if (t < N_NODES * DIM) g_zi[t] = silu_f(g_zself[t]);
}

__global__ void k_copy0(float* __restrict__ out) {
    int t = blockIdx.x * blockDim.x + threadIdx.x;
    if (t < N_NODES * DIM) {
        int n = t >> 7, d = t & 127;
        out[N_NODES * DIM + n * 2 * DIM + d] = g_zi[t];
    }
}

__global__ void k_copy1(float* __restrict__ out) {
    int t = blockIdx.x * blockDim.x + threadIdx.x;
    if (t < N_NODES * DIM) {
        int n = t >> 7, d = t & 127;
        float v = g_zi[t];
        out[t] = v;
        out[N_NODES * DIM + n * 2 * DIM + DIM + d] = v;
    }
}

// ---------------- SGEMM: BM=128, BN=128, BK=16, 256 threads, 8x8/thread ----
// C = epi(A[MxK] @ B[KxN]); bias optional, act=silu optional, Cadd residual optional.
// OUTHALF=1 -> C is __half*, else float*.
template<int OUTHALF>
__global__ __launch_bounds__(256, 2) void k_gemm2(
    const float* __restrict__ A, const float* __restrict__ B,
    const float* __restrict__ bias, const float* __restrict__ Cadd,
    void* __restrict__ Cv,
    int M, int K, int lda, int ldb, int ldc, int act)
{
    __shared__ float As[16][136];   // A^T tile (k, m), padded
    __shared__ float Bs[16][128];   // B tile   (k, n)

    const int t    = threadIdx.x;
    const int warp = t >> 5, lane = t & 31;
    const int wr = warp & 3, wc = warp >> 2;    // 4 warp-rows x 2 warp-cols
    const int lr = lane >> 3, lc = lane & 7;    // 4 lane-rows x 8 lane-cols
    const int row0 = wr * 32 + lr * 8;          // 8 rows per thread
    const int col0 = wc * 64 + lc * 8;          // 8 cols per thread
    const int m0 = blockIdx.y * 128, n0 = blockIdx.x * 128;

    // loaders
    const int arow = t >> 1;          // 0..127
    const int ak   = (t & 1) * 8;     // k offset 0 or 8
    const int brow = t >> 4;          // 0..15
    const int bcol = (t & 15) * 8;    // 0..120

    float acc[8][8];
    #pragma unroll
    for (int i = 0; i < 8; i++)
        #pragma unroll
        for (int j = 0; j < 8; j++) acc[i][j] = 0.0f;

    for (int k0 = 0; k0 < K; k0 += 16) {
        float4 a0 = make_float4(0.f,0.f,0.f,0.f), a1 = a0;
        const int gm = m0 + arow;
        if (gm < M) {
            a0 = *(const float4*)&A[(size_t)gm * lda + k0 + ak];
            a1 = *(const float4*)&A[(size_t)gm * lda + k0 + ak + 4];
        }
        float4 b0 = *(const float4*)&B[(size_t)(k0 + brow) * ldb + n0 + bcol];
        float4 b1 = *(const float4*)&B[(size_t)(k0 + brow) * ldb + n0 + bcol + 4];

        __syncthreads();
        As[ak+0][arow] = a0.x; As[ak+1][arow] = a0.y;
        As[ak+2][arow] = a0.z; As[ak+3][arow] = a0.w;
        As[ak+4][arow] = a1.x; As[ak+5][arow] = a1.y;
        As[ak+6][arow] = a1.z; As[ak+7][arow] = a1.w;
        *(float4*)&Bs[brow][bcol]     = b0;
        *(float4*)&Bs[brow][bcol + 4] = b1;
        __syncthreads();

        #pragma unroll
        for (int kk = 0; kk < 16; kk++) {
            float4 x0 = *(float4*)&As[kk][row0];
            float4 x1 = *(float4*)&As[kk][row0 + 4];
            float4 y0 = *(float4*)&Bs[kk][col0];
            float4 y1 = *(float4*)&Bs[kk][col0 + 4];
            float ar[8] = {x0.x,x0.y,x0.z,x0.w,x1.x,x1.y,x1.z,x1.w};
            float br[8] = {y0.x,y0.y,y0.z,y0.w,y1.x,y1.y,y1.z,y1.w};
            #pragma unroll
            for (int i = 0; i < 8; i++)
                #pragma unroll
                for (int j = 0; j < 8; j++)
                    acc[i][j] += ar[i] * br[j];
        }
    }

    // epilogue
    float bv[8];
    #pragma unroll
    for (int j = 0; j < 8; j++) bv[j] = bias ? bias[n0 + col0 + j] : 0.0f;

    #pragma unroll
    for (int i = 0; i < 8; i++) {
        int m = m0 + row0 + i;
        if (m >= M) continue;
        float v[8];
        #pragma unroll
        for (int j = 0; j < 8; j++) {
            float x = acc[i][j] + bv[j];
            if (act) x = silu_f(x);
            v[j] = x;
        }
        if (Cadd) {
            const float4* rp = (const float4*)&Cadd[(size_t)m * ldc + n0 + col0];
            float4 r0 = rp[0], r1 = rp[1];
            v[0]+=r0.x; v[1]+=r0.y; v[2]+=r0.z; v[3]+=r0.w;
            v[4]+=r1.x; v[5]+=r1.y; v[6]+=r1.z; v[7]+=r1.w;
        }
        if (OUTHALF) {
            __half2* cp = (__half2*)((__half*)Cv + (size_t)m * ldc + n0 + col0);
            cp[0] = __floats2half2_rn(v[0], v[1]);
            cp[1] = __floats2half2_rn(v[2], v[3]);
            cp[2] = __floats2half2_rn(v[4], v[5]);
            cp[3] = __floats2half2_rn(v[6], v[7]);
        } else {
            float* cp = (float*)Cv + (size_t)m * ldc + n0 + col0;
            ((float4*)cp)[0] = make_float4(v[0], v[1], v[2], v[3]);
            ((float4*)cp)[1] = make_float4(v[4], v[5], v[6], v[7]);
        }
    }
}

// ---------------- edge kernel ----------------
// Half-warp (16 lanes) per edge: mij[d] = sum_b s_b*sw * U[dst][b][d]  (U fp16),
// vector-reduce into zself[src]. 2 edges per warp, 16 edges per block.
__global__ __launch_bounds__(256) void k_edge(
    const int* __restrict__ esrc, const int* __restrict__ edst,
    const float* __restrict__ dist, const float* __restrict__ sw,
    const __half* __restrict__ U)
{
    const int warp = threadIdx.x >> 5;
    const int lane = threadIdx.x & 31;
    const int hl   = lane & 15;                     // lane in half-warp
    const int e    = (blockIdx.x * 8 + warp) * 2 + (lane >> 4);

    const int src = esrc[e];
    const int dst = edst[e];

    // radial basis * switch; lane's basis index = hl
    float sval;
    {
        const float sigma  = 0.8f / 15.0f;
        const float rsigma = 15.0f / 0.8f;
        float rinv = 1.0f / dist[e];
        float mu = 0.2f + (float)hl * sigma;
        float x = (rinv - mu) * rsigma;
        sval = __expf(-0.5f * x * x) * sw[e];
    }

    // U row: 2048 halves = 256 uint4. Lane hl owns d = hl*8..hl*8+7 (one uint4 per b).
    const uint4* Up = (const uint4*)(U + (size_t)dst * UW);
    float acc[8];
    #pragma unroll
    for (int i = 0; i < 8; i++) acc[i] = 0.0f;

    #pragma unroll
    for (int b = 0; b < 16; b++) {
        float sb = __shfl_sync(0xffffffffu, sval, (lane & 16) | b);
        uint4 u = Up[b * 16 + hl];
        float2 f0 = __half22float2(*(__half2*)&u.x);
        float2 f1 = __half22float2(*(__half2*)&u.y);
        float2 f2 = __half22float2(*(__half2*)&u.z);
        float2 f3 = __half22float2(*(__half2*)&u.w);
        acc[0] += sb * f0.x; acc[1] += sb * f0.y;
        acc[2] += sb * f1.x; acc[3] += sb * f1.y;
        acc[4] += sb * f2.x; acc[5] += sb * f2.y;
        acc[6] += sb * f3.x; acc[7] += sb * f3.y;
    }

    float* zp = &g_zself[(size_t)src * DIM + hl * 8];
    asm volatile("red.global.add.v4.f32 [%0], {%1,%2,%3,%4};"
                 :: "l"(zp), "f"(acc[0]), "f"(acc[1]), "f"(acc[2]), "f"(acc[3]) : "memory");
    asm volatile("red.global.add.v4.f32 [%0], {%1,%2,%3,%4};"
                 :: "l"(zp + 4), "f"(acc[4]), "f"(acc[5]), "f"(acc[6]), "f"(acc[7]) : "memory");
}

// ---------------- host driver ----------------
extern "C" void kernel_launch(void* const* d_in, const int* in_sizes, int n_in,
                              void* d_out, int out_size)
{
    const int*   species = (const int*)  d_in[0];
    const int*   esrc    = (const int*)  d_in[1];
    const int*   edst    = (const int*)  d_in[2];
    const float* dist    = (const float*)d_in[3];
    const float* swp     = (const float*)d_in[4];
    const float* Z       = (const float*)d_in[5];
    const float* Ws0     = (const float*)d_in[6];
    const float* bs0     = (const float*)d_in[7];
    const float* V0      = (const float*)d_in[8];
    const float* Ws1     = (const float*)d_in[9];
    const float* bs1     = (const float*)d_in[10];
    const float* V1      = (const float*)d_in[11];
    const float* Won_a   = (const float*)d_in[12];
    const float* bon_a   = (const float*)d_in[13];
    const float* Won_b   = (const float*)d_in[14];
    const float* bon_b   = (const float*)d_in[15];
    float* out = (float*)d_out;

    float *zi16, *zi, *zself, *h, *Vt;
    __half *Uh;
    cudaGetSymbolAddress((void**)&zi16,  g_zi16);
    cudaGetSymbolAddress((void**)&zi,    g_zi);
    cudaGetSymbolAddress((void**)&zself, g_zself);
    cudaGetSymbolAddress((void**)&h,     g_h);
    cudaGetSymbolAddress((void**)&Uh,    g_Uh);
    cudaGetSymbolAddress((void**)&Vt,    g_Vt);

    const int ND = N_NODES * DIM;
    const int MB = (N_NODES + 127) / 128;          // 157
    dim3 gemm128(1,  MB);                          // N=128
    dim3 gemmU  (UW / 128, MB);                    // N=2048

    // ---- layer 0 ----
    k_embed<<<(N_NODES * ZD + 255) / 256, 256>>>(species, Z);
    k_transpose<<<(ZD * UW + 255) / 256, 256>>>(V0, ZD);

    k_gemm2<0><<<gemm128, 256>>>(zi16, Ws0, bs0, nullptr, zself,
                                 N_NODES, ZD, ZD, DIM, DIM, 0);
    k_gemm2<1><<<gemmU, 256>>>(zi16, Vt, nullptr, nullptr, Uh,
                               N_NODES, ZD, ZD, UW, UW, 0);

    k_edge<<<N_EDGES / 16, 256>>>(esrc, edst, dist, swp, Uh);
    k_silu_zself<<<(ND + 255) / 256, 256>>>();

    for (int j = 0; j < 3; j++) {
        const float* Wa = Won_a + (size_t)(0 * 3 + j) * DIM * DIM;
        const float* ba = bon_a + (size_t)(0 * 3 + j) * DIM;
        const float* Wb = Won_b + (size_t)(0 * 3 + j) * DIM * DIM;
        const float* bb = bon_b + (size_t)(0 * 3 + j) * DIM;
        k_gemm2<0><<<gemm128, 256>>>(zi, Wa, ba, nullptr, h,
                                     N_NODES, DIM, DIM, DIM, DIM, 1);
        k_gemm2<0><<<gemm128, 256>>>(h, Wb, bb, zi, zi,
                                     N_NODES, DIM, DIM, DIM, DIM, 0);
    }
    k_copy0<<<(ND + 255) / 256, 256>>>(out);

    // ---- layer 1 ----
    k_transpose<<<(DIM * UW + 255) / 256, 256>>>(V1, DIM);

    k_gemm2<0><<<gemm128, 256>>>(zi, Ws1, bs1, nullptr, zself,
                                 N_NODES, DIM, DIM, DIM, DIM, 0);
    k_gemm2<1><<<gemmU, 256>>>(zi, Vt, nullptr, nullptr, Uh,
                               N_NODES, DIM, DIM, UW, UW, 0);

    k_edge<<<N_EDGES / 16, 256>>>(esrc, edst, dist, swp, Uh);
    k_silu_zself<<<(ND + 255) / 256, 256>>>();

    for (int j = 0; j < 3; j++) {
        const float* Wa = Won_a + (size_t)(1 * 3 + j) * DIM * DIM;
        const float* ba = bon_a + (size_t)(1 * 3 + j) * DIM;
        const float* Wb = Won_b + (size_t)(1 * 3 + j) * DIM * DIM;
        const float* bb = bon_b + (size_t)(1 * 3 + j) * DIM;
        k_gemm2<0><<<gemm128, 256>>>(zi, Wa, ba, nullptr, h,
                                     N_NODES, DIM, DIM, DIM, DIM, 1);
        k_gemm2<0><<<gemm128, 256>>>(h, Wb, bb, zi, zi,
                                     N_NODES, DIM, DIM, DIM, DIM, 0);
    }
    k_copy1<<<(ND + 255) / 256, 256>>>(out);
}

// round 3
// speedup vs baseline: 1.6052x; 1.1071x over previous
#include <cuda_runtime.h>
#include <cuda_fp16.h>
#include <math.h>

#define N_NODES 20000
#define N_EDGES 400000
#define DIM 128
#define NB 16
#define ZD 16
#define UW (NB*DIM)   // 2048

// ---------------- device scratch (static, no allocations) ----------------
__device__ float  g_zi16[N_NODES*ZD];
__device__ float  g_zi[N_NODES*DIM];
__device__ float  g_zself[N_NODES*DIM];
__device__ float  g_h[N_NODES*DIM];
__device__ __half g_Uh[(size_t)N_NODES*UW];     // U[n][b][d] fp16
__device__ __half g_Vth[DIM*UW];                // V^T fp16 (K x NB*DIM)
__device__ __half g_zih[N_NODES*DIM];           // fp16 copy of activations
__device__ float  g_S[(size_t)N_EDGES*NB];      // radial basis * switch
__device__ int    g_deg[N_NODES+1];
__device__ int    g_off[N_NODES+1];
__device__ int    g_cur[N_NODES];
__device__ int    g_eid[N_EDGES];

__device__ __forceinline__ float silu_f(float x) {
    return x / (1.0f + __expf(-x));
}

// ---------------- small kernels ----------------
__global__ void k_embed(const int* __restrict__ species, const float* __restrict__ Z) {
    int t = blockIdx.x * blockDim.x + threadIdx.x;
    if (t < N_NODES * ZD) {
        int n = t >> 4, k = t & 15;
        g_zi16[t] = Z[species[n] * ZD + k];
    }
}

// V: (NB, K, DIM) -> g_Vth: (K, NB*DIM) fp16
__global__ void k_transpose(const float* __restrict__ V, int K) {
    int t = blockIdx.x * blockDim.x + threadIdx.x;
    if (t < K * UW) {
        int j = t % UW;
        int k = t / UW;
        int b = j >> 7, d = j & 127;
        g_Vth[t] = __float2half(V[((size_t)b * K + k) * DIM + d]);
    }
}

__global__ void k_f2h(const float* __restrict__ src, __half* __restrict__ dst, int n) {
    int t = blockIdx.x * blockDim.x + threadIdx.x;
    if (t < n) dst[t] = __float2half(src[t]);
}

__global__ void k_silu_zself() {
    int t = blockIdx.x * blockDim.x + threadIdx.x;
    if (t < N_NODES * DIM) g_zi[t] = silu_f(g_zself[t]);
}

__global__ void k_copy0(float* __restrict__ out) {
    int t = blockIdx.x * blockDim.x + threadIdx.x;
    if (t < N_NODES * DIM) {
        int n = t >> 7, d = t & 127;
        out[N_NODES * DIM + n * 2 * DIM + d] = g_zi[t];
    }
}

__global__ void k_copy1(float* __restrict__ out) {
    int t = blockIdx.x * blockDim.x + threadIdx.x;
    if (t < N_NODES * DIM) {
        int n = t >> 7, d = t & 127;
        float v = g_zi[t];
        out[t] = v;
        out[N_NODES * DIM + n * 2 * DIM + DIM + d] = v;
    }
}

// ---------------- CSR build (by dst) ----------------
__global__ void k_zero_deg() {
    int t = blockIdx.x * blockDim.x + threadIdx.x;
    if (t <= N_NODES) g_deg[t] = 0;
}
__global__ void k_count(const int* __restrict__ edst) {
    int e = blockIdx.x * blockDim.x + threadIdx.x;
    if (e < N_EDGES) atomicAdd(&g_deg[edst[e]], 1);
}
__global__ void k_scan() {   // single block, 256 threads
    __shared__ int ps[256];
    const int t = threadIdx.x;
    const int CH = (N_NODES + 255) / 256;   // 79
    int base = t * CH;
    int s = 0;
    for (int i = 0; i < CH; i++) {
        int idx = base + i;
        if (idx < N_NODES) s += g_deg[idx];
    }
    ps[t] = s;
    __syncthreads();
    for (int d = 1; d < 256; d <<= 1) {
        int v = (t >= d) ? ps[t - d] : 0;
        __syncthreads();
        ps[t] += v;
        __syncthreads();
    }
    int run = (t > 0) ? ps[t - 1] : 0;
    for (int i = 0; i < CH; i++) {
        int idx = base + i;
        if (idx < N_NODES) {
            g_off[idx] = run;
            g_cur[idx] = run;
            run += g_deg[idx];
        }
    }
    if (t == 255) g_off[N_NODES] = ps[255];
}
__global__ void k_fill(const int* __restrict__ edst) {
    int e = blockIdx.x * blockDim.x + threadIdx.x;
    if (e < N_EDGES) {
        int pos = atomicAdd(&g_cur[edst[e]], 1);
        g_eid[pos] = e;
    }
}
__global__ void k_sbasis(const float* __restrict__ dist, const float* __restrict__ sw) {
    int t = blockIdx.x * blockDim.x + threadIdx.x;
    if (t < N_EDGES * NB) {
        int e = t >> 4, b = t & 15;
        const float sigma  = 0.8f / 15.0f;
        const float rsigma = 15.0f / 0.8f;
        float rinv = 1.0f / dist[e];
        float mu = 0.2f + (float)b * sigma;
        float x = (rinv - mu) * rsigma;
        g_S[t] = __expf(-0.5f * x * x) * sw[e];
    }
}

// ---------------- fp32 SGEMM (zself + onsite), BM=BN=128, 8x8/thread ------
template<int OUTHALF>
__global__ __launch_bounds__(256, 2) void k_gemm2(
    const float* __restrict__ A, const float* __restrict__ B,
    const float* __restrict__ bias, const float* __restrict__ Cadd,
    void* __restrict__ Cv,
    int M, int K, int lda, int ldb, int ldc, int act)
{
    __shared__ float As[16][136];
    __shared__ float Bs[16][128];

    const int t    = threadIdx.x;
    const int warp = t >> 5, lane = t & 31;
    const int wr = warp & 3, wc = warp >> 2;
    const int lr = lane >> 3, lc = lane & 7;
    const int row0 = wr * 32 + lr * 8;
    const int col0 = wc * 64 + lc * 8;
    const int m0 = blockIdx.y * 128, n0 = blockIdx.x * 128;

    const int arow = t >> 1;
    const int ak   = (t & 1) * 8;
    const int brow = t >> 4;
    const int bcol = (t & 15) * 8;

    float acc[8][8];
    #pragma unroll
    for (int i = 0; i < 8; i++)
        #pragma unroll
        for (int j = 0; j < 8; j++) acc[i][j] = 0.0f;

    for (int k0 = 0; k0 < K; k0 += 16) {
        float4 a0 = make_float4(0.f,0.f,0.f,0.f), a1 = a0;
        const int gm = m0 + arow;
        if (gm < M) {
            a0 = *(const float4*)&A[(size_t)gm * lda + k0 + ak];
            a1 = *(const float4*)&A[(size_t)gm * lda + k0 + ak + 4];
        }
        float4 b0 = *(const float4*)&B[(size_t)(k0 + brow) * ldb + n0 + bcol];
        float4 b1 = *(const float4*)&B[(size_t)(k0 + brow) * ldb + n0 + bcol + 4];

        __syncthreads();
        As[ak+0][arow] = a0.x; As[ak+1][arow] = a0.y;
        As[ak+2][arow] = a0.z; As[ak+3][arow] = a0.w;
        As[ak+4][arow] = a1.x; As[ak+5][arow] = a1.y;
        As[ak+6][arow] = a1.z; As[ak+7][arow] = a1.w;
        *(float4*)&Bs[brow][bcol]     = b0;
        *(float4*)&Bs[brow][bcol + 4] = b1;
        __syncthreads();

        #pragma unroll
        for (int kk = 0; kk < 16; kk++) {
            float4 x0 = *(float4*)&As[kk][row0];
            float4 x1 = *(float4*)&As[kk][row0 + 4];
            float4 y0 = *(float4*)&Bs[kk][col0];
            float4 y1 = *(float4*)&Bs[kk][col0 + 4];
            float ar[8] = {x0.x,x0.y,x0.z,x0.w,x1.x,x1.y,x1.z,x1.w};
            float br[8] = {y0.x,y0.y,y0.z,y0.w,y1.x,y1.y,y1.z,y1.w};
            #pragma unroll
            for (int i = 0; i < 8; i++)
                #pragma unroll
                for (int j = 0; j < 8; j++)
                    acc[i][j] += ar[i] * br[j];
        }
    }

    float bv[8];
    #pragma unroll
    for (int j = 0; j < 8; j++) bv[j] = bias ? bias[n0 + col0 + j] : 0.0f;

    #pragma unroll
    for (int i = 0; i < 8; i++) {
        int m = m0 + row0 + i;
        if (m >= M) continue;
        float v[8];
        #pragma unroll
        for (int j = 0; j < 8; j++) {
            float x = acc[i][j] + bv[j];
            if (act) x = silu_f(x);
            v[j] = x;
        }
        if (Cadd) {
            const float4* rp = (const float4*)&Cadd[(size_t)m * ldc + n0 + col0];
            float4 r0 = rp[0], r1 = rp[1];
            v[0]+=r0.x; v[1]+=r0.y; v[2]+=r0.z; v[3]+=r0.w;
            v[4]+=r1.x; v[5]+=r1.y; v[6]+=r1.z; v[7]+=r1.w;
        }
        if (OUTHALF) {
            __half2* cp = (__half2*)((__half*)Cv + (size_t)m * ldc + n0 + col0);
            cp[0] = __floats2half2_rn(v[0], v[1]);
            cp[1] = __floats2half2_rn(v[2], v[3]);
            cp[2] = __floats2half2_rn(v[4], v[5]);
            cp[3] = __floats2half2_rn(v[6], v[7]);
        } else {
            float* cp = (float*)Cv + (size_t)m * ldc + n0 + col0;
            ((float4*)cp)[0] = make_float4(v[0], v[1], v[2], v[3]);
            ((float4*)cp)[1] = make_float4(v[4], v[5], v[6], v[7]);
        }
    }
}

// ---------------- fp16 tensor-core GEMM (U-GEMM): C_h = A_h @ B_h ---------
// BM=128, BN=128, 256 thr (8 warps, 4m x 2n), warp tile 32x64, mma m16n8k16.
__global__ __launch_bounds__(256, 2) void k_hgemm(
    const __half* __restrict__ A, const __half* __restrict__ B,
    __half* __restrict__ C, int M, int K, int ldb)
{
    __shared__ __half As[128][40];   // rows padded to 40 halves (80B)
    __shared__ __half Bs[32][136];   // rows padded to 136 halves (272B)

    const int t    = threadIdx.x;
    const int warp = t >> 5, lane = t & 31;
    const int wm = (warp & 3) * 32;
    const int wn = (warp >> 2) * 64;
    const int m0 = blockIdx.y * 128, n0 = blockIdx.x * 128;

    const int arow = t >> 1, ak = (t & 1) * 8;
    const int brow = t >> 4, bcol = (t & 15) * 8;

    float acc[2][8][4];
    #pragma unroll
    for (int mt = 0; mt < 2; mt++)
        #pragma unroll
        for (int nt = 0; nt < 8; nt++)
            #pragma unroll
            for (int i = 0; i < 4; i++) acc[mt][nt][i] = 0.0f;

    const uint4 z4 = make_uint4(0,0,0,0);

    for (int k0 = 0; k0 < K; k0 += 32) {
        const int nsub = (K - k0 >= 32) ? 2 : 1;
        uint4 av0 = z4, av1 = z4, bv0, bv1;
        const int gm = m0 + arow;
        if (gm < M) {
            av0 = *(const uint4*)&A[(size_t)gm * K + k0 + ak];
            if (nsub == 2) av1 = *(const uint4*)&A[(size_t)gm * K + k0 + 16 + ak];
        }
        bv0 = *(const uint4*)&B[(size_t)(k0 + brow) * ldb + n0 + bcol];
        if (nsub == 2) bv1 = *(const uint4*)&B[(size_t)(k0 + 16 + brow) * ldb + n0 + bcol];

        __syncthreads();
        *(uint4*)&As[arow][ak] = av0;
        if (nsub == 2) *(uint4*)&As[arow][16 + ak] = av1;
        *(uint4*)&Bs[brow][bcol] = bv0;
        if (nsub == 2) *(uint4*)&Bs[16 + brow][bcol] = bv1;
        __syncthreads();

        #pragma unroll
        for (int sub = 0; sub < 2; sub++) {
            if (sub >= nsub) break;
            const int kc = sub * 16;

            // A fragments: 2 m16k16 tiles
            unsigned af[2][4];
            #pragma unroll
            for (int mt = 0; mt < 2; mt++) {
                const __half* p = &As[wm + mt*16 + (lane & 15)][kc + ((lane >> 4) << 3)];
                unsigned addr = (unsigned)__cvta_generic_to_shared(p);
                asm volatile("ldmatrix.sync.aligned.m8n8.x4.shared.b16 {%0,%1,%2,%3}, [%4];"
                    : "=r"(af[mt][0]), "=r"(af[mt][1]), "=r"(af[mt][2]), "=r"(af[mt][3])
                    : "r"(addr));
            }
            // B fragments: 8 k16n8 tiles, loaded as 4 x4.trans
            unsigned bf[8][2];
            #pragma unroll
            for (int q = 0; q < 4; q++) {
                const __half* p = &Bs[kc + (lane & 15)][wn + q*16 + ((lane >> 4) << 3)];
                unsigned addr = (unsigned)__cvta_generic_to_shared(p);
                asm volatile("ldmatrix.sync.aligned.m8n8.x4.trans.shared.b16 {%0,%1,%2,%3}, [%4];"
                    : "=r"(bf[q*2][0]), "=r"(bf[q*2][1]), "=r"(bf[q*2+1][0]), "=r"(bf[q*2+1][1])
                    : "r"(addr));
            }
            #pragma unroll
            for (int mt = 0; mt < 2; mt++)
                #pragma unroll
                for (int nt = 0; nt < 8; nt++) {
                    asm volatile(
                        "mma.sync.aligned.m16n8k16.row.col.f32.f16.f16.f32 "
                        "{%0,%1,%2,%3}, {%4,%5,%6,%7}, {%8,%9}, {%0,%1,%2,%3};"
                        : "+f"(acc[mt][nt][0]), "+f"(acc[mt][nt][1]),
                          "+f"(acc[mt][nt][2]), "+f"(acc[mt][nt][3])
                        : "r"(af[mt][0]), "r"(af[mt][1]), "r"(af[mt][2]), "r"(af[mt][3]),
                          "r"(bf[nt][0]), "r"(bf[nt][1]));
                }
        }
    }

    // epilogue: store fp16
    const int g = lane >> 2, t4 = lane & 3;
    #pragma unroll
    for (int mt = 0; mt < 2; mt++) {
        #pragma unroll
        for (int nt = 0; nt < 8; nt++) {
            int r0 = m0 + wm + mt*16 + g;
            int col = n0 + wn + nt*8 + 2*t4;
            if (r0 < M)
                *(__half2*)&C[(size_t)r0 * ldb + col] =
                    __floats2half2_rn(acc[mt][nt][0], acc[mt][nt][1]);
            if (r0 + 8 < M)
                *(__half2*)&C[(size_t)(r0+8) * ldb + col] =
                    __floats2half2_rn(acc[mt][nt][2], acc[mt][nt][3]);
        }
    }
}

// ---------------- edge kernel: warp per dst-node, CSR ----------------
__global__ __launch_bounds__(256) void k_edge_csr(const int* __restrict__ esrc) {
    const int warp = threadIdx.x >> 5;
    const int lane = threadIdx.x & 31;
    const int n = blockIdx.x * 8 + warp;
    if (n >= N_NODES) return;
    const int e0 = g_off[n], e1 = g_off[n + 1];
    if (e0 == e1) return;

    // load U[n] row once: lane owns d = lane*4 .. +3, all 16 bases
    float u[16][4];
    const uint2* Up = (const uint2*)(g_Uh + (size_t)n * UW);
    #pragma unroll
    for (int b = 0; b < 16; b++) {
        uint2 q = Up[b * 32 + lane];
        float2 f0 = __half22float2(*(__half2*)&q.x);
        float2 f1 = __half22float2(*(__half2*)&q.y);
        u[b][0] = f0.x; u[b][1] = f0.y; u[b][2] = f1.x; u[b][3] = f1.y;
    }

    for (int p = e0; p < e1; p++) {
        const int e = g_eid[p];
        const int src = esrc[e];
        float sv = (lane < 16) ? g_S[(size_t)e * NB + lane] : 0.0f;
        float m0 = 0.f, m1 = 0.f, m2 = 0.f, m3 = 0.f;
        #pragma unroll
        for (int b = 0; b < 16; b++) {
            float sb = __shfl_sync(0xffffffffu, sv, b);
            m0 += sb * u[b][0];
            m1 += sb * u[b][1];
            m2 += sb * u[b][2];
            m3 += sb * u[b][3];
        }
        float* zp = &g_zself[(size_t)src * DIM + lane * 4];
        asm volatile("red.global.add.v4.f32 [%0], {%1,%2,%3,%4};"
                     :: "l"(zp), "f"(m0), "f"(m1), "f"(m2), "f"(m3) : "memory");
    }
}

// ---------------- host driver ----------------
extern "C" void kernel_launch(void* const* d_in, const int* in_sizes, int n_in,
                              void* d_out, int out_size)
{
    const int*   species = (const int*)  d_in[0];
    const int*   esrc    = (const int*)  d_in[1];
    const int*   edst    = (const int*)  d_in[2];
    const float* dist    = (const float*)d_in[3];
    const float* swp     = (const float*)d_in[4];
    const float* Z       = (const float*)d_in[5];
    const float* Ws0     = (const float*)d_in[6];
    const float* bs0     = (const float*)d_in[7];
    const float* V0      = (const float*)d_in[8];
    const float* Ws1     = (const float*)d_in[9];
    const float* bs1     = (const float*)d_in[10];
    const float* V1      = (const float*)d_in[11];
    const float* Won_a   = (const float*)d_in[12];
    const float* bon_a   = (const float*)d_in[13];
    const float* Won_b   = (const float*)d_in[14];
    const float* bon_b   = (const float*)d_in[15];
    float* out = (float*)d_out;

    float *zi16, *zi, *zself, *h;
    __half *Uh, *Vth, *zih;
    cudaGetSymbolAddress((void**)&zi16,  g_zi16);
    cudaGetSymbolAddress((void**)&zi,    g_zi);
    cudaGetSymbolAddress((void**)&zself, g_zself);
    cudaGetSymbolAddress((void**)&h,     g_h);
    cudaGetSymbolAddress((void**)&Uh,    g_Uh);
    cudaGetSymbolAddress((void**)&Vth,   g_Vth);
    cudaGetSymbolAddress((void**)&zih,   g_zih);

    const int ND = N_NODES * DIM;
    const int MB = (N_NODES + 127) / 128;
    dim3 gemm128(1,  MB);
    dim3 gemmU  (UW / 128, MB);
    const int EB = (N_EDGES + 255) / 256;

    // ---- graph preprocessing (reused by both layers) ----
    k_zero_deg<<<(N_NODES + 256) / 256, 256>>>();
    k_count<<<EB, 256>>>(edst);
    k_scan<<<1, 256>>>();
    k_fill<<<EB, 256>>>(edst);
    k_sbasis<<<(N_EDGES * NB + 255) / 256, 256>>>(dist, swp);

    // ---- layer 0 ----
    k_embed<<<(N_NODES * ZD + 255) / 256, 256>>>(species, Z);
    k_transpose<<<(ZD * UW + 255) / 256, 256>>>(V0, ZD);
    k_f2h<<<(N_NODES * ZD + 255) / 256, 256>>>(zi16, zih, N_NODES * ZD);

    k_gemm2<0><<<gemm128, 256>>>(zi16, Ws0, bs0, nullptr, zself,
                                 N_NODES, ZD, ZD, DIM, DIM, 0);
    k_hgemm<<<gemmU, 256>>>(zih, Vth, Uh, N_NODES, ZD, UW);

    k_edge_csr<<<(N_NODES + 7) / 8, 256>>>(esrc);
    k_silu_zself<<<(ND + 255) / 256, 256>>>();

    for (int j = 0; j < 3; j++) {
        const float* Wa = Won_a + (size_t)(0 * 3 + j) * DIM * DIM;
        const float* ba = bon_a + (size_t)(0 * 3 + j) * DIM;
        const float* Wb = Won_b + (size_t)(0 * 3 + j) * DIM * DIM;
        const float* bb = bon_b + (size_t)(0 * 3 + j) * DIM;
        k_gemm2<0><<<gemm128, 256>>>(zi, Wa, ba, nullptr, h,
                                     N_NODES, DIM, DIM, DIM, DIM, 1);
        k_gemm2<0><<<gemm128, 256>>>(h, Wb, bb, zi, zi,
                                     N_NODES, DIM, DIM, DIM, DIM, 0);
    }
    k_copy0<<<(ND + 255) / 256, 256>>>(out);

    // ---- layer 1 ----
    k_transpose<<<(DIM * UW + 255) / 256, 256>>>(V1, DIM);
    k_f2h<<<(ND + 255) / 256, 256>>>(zi, zih, ND);

    k_gemm2<0><<<gemm128, 256>>>(zi, Ws1, bs1, nullptr, zself,
                                 N_NODES, DIM, DIM, DIM, DIM, 0);
    k_hgemm<<<gemmU, 256>>>(zih, Vth, Uh, N_NODES, DIM, UW);

    k_edge_csr<<<(N_NODES + 7) / 8, 256>>>(esrc);
    k_silu_zself<<<(ND + 255) / 256, 256>>>();

    for (int j = 0; j < 3; j++) {
        const float* Wa = Won_a + (size_t)(1 * 3 + j) * DIM * DIM;
        const float* ba = bon_a + (size_t)(1 * 3 + j) * DIM;
        const float* Wb = Won_b + (size_t)(1 * 3 + j) * DIM * DIM;
        const float* bb = bon_b + (size_t)(1 * 3 + j) * DIM;
        k_gemm2<0><<<gemm128, 256>>>(zi, Wa, ba, nullptr, h,
                                     N_NODES, DIM, DIM, DIM, DIM, 1);
        k_gemm2<0><<<gemm128, 256>>>(h, Wb, bb, zi, zi,
                                     N_NODES, DIM, DIM, DIM, DIM, 0);
    }
    k_copy1<<<(ND + 255) / 256, 256>>>(out);
}